// round 1
// baseline (speedup 1.0000x reference)
#include <cuda_runtime.h>
#include <math.h>

#define BATCH 8
#define SEQ   4096
#define DIN   64
#define HID   512
#define M_ROWS (BATCH*SEQ)

#define TQ 64
#define TK 64
#define RSCALE 0.044194173824159216f  /* 1/sqrt(512) */

// ---------------- global scratch (allocation-free rule) ----------------
__device__ float g_Q[BATCH*SEQ*HID];
__device__ float g_K[BATCH*SEQ*HID];
__device__ float g_V[BATCH*SEQ*HID];

// ---------------- fused QKV projection ----------------
// grid: (M/128, HID/128, 3); block 256; dyn smem 64KB
__global__ __launch_bounds__(256) void qkv_proj_kernel(
    const float* __restrict__ x,
    const float* __restrict__ Wq, const float* __restrict__ bq,
    const float* __restrict__ Wk, const float* __restrict__ bk,
    const float* __restrict__ Wv, const float* __restrict__ bv)
{
    extern __shared__ float psm[];
    float* sX = psm;            // [128][64]
    float* sW = psm + 128*64;   // [64][128]

    const float* Wsel; const float* bsel; float* osel;
    if (blockIdx.z == 0)      { Wsel = Wq; bsel = bq; osel = g_Q; }
    else if (blockIdx.z == 1) { Wsel = Wk; bsel = bk; osel = g_K; }
    else                      { Wsel = Wv; bsel = bv; osel = g_V; }

    const int row0 = blockIdx.x * 128;
    const int col0 = blockIdx.y * 128;
    const int tid  = threadIdx.x;

    #pragma unroll
    for (int i = 0; i < 8; i++) {
        int idx = i*256 + tid;               // float4 id 0..2047
        int r = idx >> 4, c4 = idx & 15;
        *(float4*)&sX[r*64 + c4*4] = *(const float4*)&x[(size_t)(row0+r)*DIN + c4*4];
    }
    #pragma unroll
    for (int i = 0; i < 8; i++) {
        int idx = i*256 + tid;
        int r = idx >> 5, c4 = idx & 31;
        *(float4*)&sW[r*128 + c4*4] = *(const float4*)&Wsel[(size_t)r*HID + col0 + c4*4];
    }
    __syncthreads();

    const int ty = tid >> 4, tx = tid & 15;
    float acc[8][8];
    #pragma unroll
    for (int i = 0; i < 8; i++)
        #pragma unroll
        for (int j = 0; j < 8; j++) acc[i][j] = 0.0f;

    #pragma unroll 8
    for (int k = 0; k < 64; k++) {
        float xr[8];
        #pragma unroll
        for (int i = 0; i < 8; i++) xr[i] = sX[(ty*8+i)*64 + k];
        float4 w0 = *(const float4*)&sW[k*128 + tx*8];
        float4 w1 = *(const float4*)&sW[k*128 + tx*8 + 4];
        #pragma unroll
        for (int i = 0; i < 8; i++) {
            acc[i][0] += xr[i]*w0.x; acc[i][1] += xr[i]*w0.y;
            acc[i][2] += xr[i]*w0.z; acc[i][3] += xr[i]*w0.w;
            acc[i][4] += xr[i]*w1.x; acc[i][5] += xr[i]*w1.y;
            acc[i][6] += xr[i]*w1.z; acc[i][7] += xr[i]*w1.w;
        }
    }

    float bb[8];
    #pragma unroll
    for (int j = 0; j < 8; j++) bb[j] = __ldg(&bsel[col0 + tx*8 + j]);

    #pragma unroll
    for (int i = 0; i < 8; i++) {
        float4 o0, o1;
        o0.x = acc[i][0]+bb[0]; o0.y = acc[i][1]+bb[1];
        o0.z = acc[i][2]+bb[2]; o0.w = acc[i][3]+bb[3];
        o1.x = acc[i][4]+bb[4]; o1.y = acc[i][5]+bb[5];
        o1.z = acc[i][6]+bb[6]; o1.w = acc[i][7]+bb[7];
        size_t base = (size_t)(row0 + ty*8 + i)*HID + col0 + tx*8;
        *(float4*)&osel[base]     = o0;
        *(float4*)&osel[base + 4] = o1;
    }
}

// ---------------- flash attention ----------------
// smem layout (floats)
#define OFF_QT 0
#define OFF_KV (512*66)                 // 33792
#define OFF_SS (OFF_KV + 64*128)        // 41984
#define SMEM_FLOATS (OFF_SS + 64*65)    // 46144  -> 184576 bytes
// grid: (SEQ/TQ, BATCH); block 512
__global__ __launch_bounds__(512, 1) void attn_kernel(float* __restrict__ out)
{
    extern __shared__ float sm[];
    float* sQT = sm + OFF_QT;   // [512][66]  transposed, pre-scaled Q
    float* sKV = sm + OFF_KV;   // [64][128]  K/V h-chunk
    float* sS  = sm + OFF_SS;   // [64][65]   scores -> probs

    const int b    = blockIdx.y;
    const int q0   = blockIdx.x * TQ;
    const int tid  = threadIdx.x;
    const int wid  = tid >> 5;   // 0..15  (owns k-rows in score phase, q-rows in softmax/PV)
    const int lane = tid & 31;

    // ---- load Q tile, transpose into sQT, fold in 1/sqrt(H) ----
    const float* Qg = g_Q + (size_t)(b*SEQ + q0) * HID;
    #pragma unroll
    for (int r = 0; r < 16; r++) {
        int idx = r*512 + tid;          // float4 id 0..8191
        int q  = idx >> 7;              // 128 float4 per row
        int h4 = idx & 127;
        float4 v = *(const float4*)&Qg[(size_t)q*HID + h4*4];
        int hb = h4*4;
        sQT[(hb+0)*66 + q] = v.x * RSCALE;
        sQT[(hb+1)*66 + q] = v.y * RSCALE;
        sQT[(hb+2)*66 + q] = v.z * RSCALE;
        sQT[(hb+3)*66 + q] = v.w * RSCALE;
    }

    float acc[4][16];
    #pragma unroll
    for (int i = 0; i < 4; i++)
        #pragma unroll
        for (int j = 0; j < 16; j++) acc[i][j] = 0.0f;

    float mrow[4], lrow[4];
    #pragma unroll
    for (int i = 0; i < 4; i++) { mrow[i] = -1e30f; lrow[i] = 0.0f; }

    const float* Kg_base = g_K + (size_t)b*SEQ*HID;
    const float* Vg_base = g_V + (size_t)b*SEQ*HID;

    for (int kt = 0; kt < SEQ/TK; kt++) {
        // ================= scores: sc[i][j] = K[wid*4+i] . Qs[2*lane+j] =================
        float sc[4][2];
        #pragma unroll
        for (int i = 0; i < 4; i++) { sc[i][0] = 0.0f; sc[i][1] = 0.0f; }

        const float* Kg = Kg_base + (size_t)kt*TK*HID;
        #pragma unroll
        for (int hc = 0; hc < 4; hc++) {
            __syncthreads();    // previous consumers of sKV done
            #pragma unroll
            for (int r = 0; r < 4; r++) {
                int idx = r*512 + tid;         // 2048 float4
                int key = idx >> 5, h4 = idx & 31;
                *(float4*)&sKV[key*128 + h4*4] =
                    *(const float4*)&Kg[(size_t)key*HID + hc*128 + h4*4];
            }
            __syncthreads();
            const float* qp = &sQT[(hc*128)*66 + 2*lane];
            const float* kp = &sKV[(wid*4)*128];
            #pragma unroll 8
            for (int h = 0; h < 128; h++) {
                float2 qv = *(const float2*)&qp[h*66];
                float k0 = kp[h];
                float k1 = kp[128 + h];
                float k2 = kp[256 + h];
                float k3 = kp[384 + h];
                sc[0][0] += k0*qv.x; sc[0][1] += k0*qv.y;
                sc[1][0] += k1*qv.x; sc[1][1] += k1*qv.y;
                sc[2][0] += k2*qv.x; sc[2][1] += k2*qv.y;
                sc[3][0] += k3*qv.x; sc[3][1] += k3*qv.y;
            }
        }
        // scatter scores into sS[q][k]
        #pragma unroll
        for (int i = 0; i < 4; i++) {
            sS[(2*lane+0)*65 + wid*4 + i] = sc[i][0];
            sS[(2*lane+1)*65 + wid*4 + i] = sc[i][1];
        }
        __syncthreads();

        // ================= online softmax: warp wid owns rows wid*4..+3 =================
        float corr[4];
        #pragma unroll
        for (int rr = 0; rr < 4; rr++) {
            int q = wid*4 + rr;
            float a0 = sS[q*65 + 2*lane];
            float a1 = sS[q*65 + 2*lane + 1];
            float mx = fmaxf(a0, a1);
            #pragma unroll
            for (int o = 16; o > 0; o >>= 1)
                mx = fmaxf(mx, __shfl_xor_sync(0xffffffffu, mx, o));
            float mnew = fmaxf(mrow[rr], mx);
            float p0 = __expf(a0 - mnew);
            float p1 = __expf(a1 - mnew);
            float s = p0 + p1;
            #pragma unroll
            for (int o = 16; o > 0; o >>= 1)
                s += __shfl_xor_sync(0xffffffffu, s, o);
            float c = __expf(mrow[rr] - mnew);
            corr[rr] = c;
            lrow[rr] = lrow[rr]*c + s;
            mrow[rr] = mnew;
            sS[q*65 + 2*lane]     = p0;
            sS[q*65 + 2*lane + 1] = p1;
        }
        #pragma unroll
        for (int i = 0; i < 4; i++)
            #pragma unroll
            for (int j = 0; j < 16; j++) acc[i][j] *= corr[i];

        // ================= PV: acc[i][hc*4+c] += P[wid*4+i][k] * V[k][h] =================
        const float* Vg = Vg_base + (size_t)kt*TK*HID;
        #pragma unroll
        for (int hc = 0; hc < 4; hc++) {
            __syncthreads();
            #pragma unroll
            for (int r = 0; r < 4; r++) {
                int idx = r*512 + tid;
                int key = idx >> 5, h4 = idx & 31;
                *(float4*)&sKV[key*128 + h4*4] =
                    *(const float4*)&Vg[(size_t)key*HID + hc*128 + h4*4];
            }
            __syncthreads();
            const float* pp = &sS[(wid*4)*65];
            #pragma unroll 4
            for (int k = 0; k < 64; k++) {
                float4 vv = *(const float4*)&sKV[k*128 + lane*4];
                float p0 = pp[k];
                float p1 = pp[65  + k];
                float p2 = pp[130 + k];
                float p3 = pp[195 + k];
                acc[0][hc*4+0] += p0*vv.x; acc[0][hc*4+1] += p0*vv.y;
                acc[0][hc*4+2] += p0*vv.z; acc[0][hc*4+3] += p0*vv.w;
                acc[1][hc*4+0] += p1*vv.x; acc[1][hc*4+1] += p1*vv.y;
                acc[1][hc*4+2] += p1*vv.z; acc[1][hc*4+3] += p1*vv.w;
                acc[2][hc*4+0] += p2*vv.x; acc[2][hc*4+1] += p2*vv.y;
                acc[2][hc*4+2] += p2*vv.z; acc[2][hc*4+3] += p2*vv.w;
                acc[3][hc*4+0] += p3*vv.x; acc[3][hc*4+1] += p3*vv.y;
                acc[3][hc*4+2] += p3*vv.z; acc[3][hc*4+3] += p3*vv.w;
            }
        }
    }

    // ================= normalize + store =================
    float invl[4];
    #pragma unroll
    for (int i = 0; i < 4; i++) invl[i] = 1.0f / lrow[i];

    float* Og = out + (size_t)(b*SEQ + q0)*HID;
    #pragma unroll
    for (int i = 0; i < 4; i++) {
        #pragma unroll
        for (int hc = 0; hc < 4; hc++) {
            float4 o;
            o.x = acc[i][hc*4+0]*invl[i];
            o.y = acc[i][hc*4+1]*invl[i];
            o.z = acc[i][hc*4+2]*invl[i];
            o.w = acc[i][hc*4+3]*invl[i];
            *(float4*)&Og[(size_t)(wid*4+i)*HID + hc*128 + lane*4] = o;
        }
    }
}

// ---------------- launcher ----------------
extern "C" void kernel_launch(void* const* d_in, const int* in_sizes, int n_in,
                              void* d_out, int out_size)
{
    const float* x  = (const float*)d_in[0];
    const float* Wq = (const float*)d_in[1];
    const float* bq = (const float*)d_in[2];
    const float* Wk = (const float*)d_in[3];
    const float* bk = (const float*)d_in[4];
    const float* Wv = (const float*)d_in[5];
    const float* bv = (const float*)d_in[6];
    float* out = (float*)d_out;

    cudaFuncSetAttribute(qkv_proj_kernel, cudaFuncAttributeMaxDynamicSharedMemorySize, 64*1024);
    cudaFuncSetAttribute(attn_kernel, cudaFuncAttributeMaxDynamicSharedMemorySize, SMEM_FLOATS*4);

    dim3 pg(M_ROWS/128, HID/128, 3);
    qkv_proj_kernel<<<pg, 256, 64*1024>>>(x, Wq, bq, Wk, bk, Wv, bv);

    dim3 ag(SEQ/TQ, BATCH);
    attn_kernel<<<ag, 512, SMEM_FLOATS*4>>>(out);
}